// round 4
// baseline (speedup 1.0000x reference)
#include <cuda_runtime.h>
#include <math.h>

// IDWT 1D (db4), banded synthesis:
//   even j=2i  : L[i+1]*bl1 + L[i]*bl3 + L[i-1]*bl5 + L[i-2]*bl7  (+ H w/ bh)
//   odd  j=2i+1: L[i+2]*bl0 + L[i+1]*bl2 + L[i]*bl4 + L[i-1]*bl6  (+ H w/ bh)
// Taps read from matrix row r=2 (band[k] at column k+1).
//
// 16 outputs per thread: 2 float4 loads from L, 2 from H, halo via warp
// shuffle, 4 float4 streaming stores.

__global__ void idwt1d_db4_kernel(const float* __restrict__ L,
                                  const float* __restrict__ H,
                                  const float* __restrict__ mL,
                                  const float* __restrict__ mH,
                                  float* __restrict__ out,
                                  int Lh)
{
    const int W = 2 * Lh;
    __shared__ float cf[16];
    if (threadIdx.x < 16) {
        const float* M = (threadIdx.x < 8) ? mL : mH;
        cf[threadIdx.x] = M[(size_t)2 * W + (threadIdx.x & 7) + 1];
    }
    __syncthreads();

    const float bl0 = cf[0], bl1 = cf[1], bl2 = cf[2], bl3 = cf[3];
    const float bl4 = cf[4], bl5 = cf[5], bl6 = cf[6], bl7 = cf[7];
    const float bh0 = cf[8], bh1 = cf[9], bh2 = cf[10], bh3 = cf[11];
    const float bh4 = cf[12], bh5 = cf[13], bh6 = cf[14], bh7 = cf[15];

    const int row = blockIdx.y;
    const int nt  = Lh >> 3;                 // threads per row (8 coarse each)
    const int t   = blockIdx.x * blockDim.x + threadIdx.x;
    if (t >= nt) return;

    const int lane = threadIdx.x & 31;
    const int c0   = 8 * t;                  // thread owns L/H[c0 .. c0+7]

    const float* __restrict__ Lr = L + (size_t)row * Lh;
    const float* __restrict__ Hr = H + (size_t)row * Lh;

    const float4 lA = *reinterpret_cast<const float4*>(Lr + c0);
    const float4 lB = *reinterpret_cast<const float4*>(Lr + c0 + 4);
    const float4 hA = *reinterpret_cast<const float4*>(Hr + c0);
    const float4 hB = *reinterpret_cast<const float4*>(Hr + c0 + 4);

    // Halo from adjacent lanes (adjacent lanes own adjacent 8-wide chunks).
    float lm2 = __shfl_up_sync(0xffffffffu, lB.z, 1);
    float lm1 = __shfl_up_sync(0xffffffffu, lB.w, 1);
    float hm2 = __shfl_up_sync(0xffffffffu, hB.z, 1);
    float hm1 = __shfl_up_sync(0xffffffffu, hB.w, 1);
    float lp8 = __shfl_down_sync(0xffffffffu, lA.x, 1);
    float lp9 = __shfl_down_sync(0xffffffffu, lA.y, 1);
    float hp8 = __shfl_down_sync(0xffffffffu, hA.x, 1);
    float hp9 = __shfl_down_sync(0xffffffffu, hA.y, 1);

    if (lane == 0) {                          // warp-edge fixups
        lm2 = (c0 >= 2) ? Lr[c0 - 2] : 0.0f;
        lm1 = (c0 >= 1) ? Lr[c0 - 1] : 0.0f;
        hm2 = (c0 >= 2) ? Hr[c0 - 2] : 0.0f;
        hm1 = (c0 >= 1) ? Hr[c0 - 1] : 0.0f;
    }
    if (lane == 31) {
        lp8 = (c0 + 8 < Lh) ? Lr[c0 + 8] : 0.0f;
        lp9 = (c0 + 9 < Lh) ? Lr[c0 + 9] : 0.0f;
        hp8 = (c0 + 8 < Lh) ? Hr[c0 + 8] : 0.0f;
        hp9 = (c0 + 9 < Lh) ? Hr[c0 + 9] : 0.0f;
    }

    // la[k] = L[c0-2+k], k=0..11
    const float la[12] = { lm2, lm1, lA.x, lA.y, lA.z, lA.w,
                           lB.x, lB.y, lB.z, lB.w, lp8, lp9 };
    const float ha[12] = { hm2, hm1, hA.x, hA.y, hA.z, hA.w,
                           hB.x, hB.y, hB.z, hB.w, hp8, hp9 };

    float o[16];
#pragma unroll
    for (int m = 0; m < 8; m++) {
        // even j = 2*(c0+m): taps la[m..m+3]
        o[2 * m] =
            fmaf(la[m + 3], bl1, fmaf(la[m + 2], bl3, fmaf(la[m + 1], bl5, la[m] * bl7))) +
            fmaf(ha[m + 3], bh1, fmaf(ha[m + 2], bh3, fmaf(ha[m + 1], bh5, ha[m] * bh7)));
        // odd j = 2*(c0+m)+1: taps la[m+1..m+4]
        o[2 * m + 1] =
            fmaf(la[m + 4], bl0, fmaf(la[m + 3], bl2, fmaf(la[m + 2], bl4, la[m + 1] * bl6))) +
            fmaf(ha[m + 4], bh0, fmaf(ha[m + 3], bh2, fmaf(ha[m + 2], bh4, ha[m + 1] * bh6)));
    }

    float4* op = reinterpret_cast<float4*>(out + (size_t)row * W + 16 * (size_t)t);
    __stcs(op,     make_float4(o[0],  o[1],  o[2],  o[3]));
    __stcs(op + 1, make_float4(o[4],  o[5],  o[6],  o[7]));
    __stcs(op + 2, make_float4(o[8],  o[9],  o[10], o[11]));
    __stcs(op + 3, make_float4(o[12], o[13], o[14], o[15]));
}

extern "C" void kernel_launch(void* const* d_in, const int* in_sizes, int n_in,
                              void* d_out, int out_size)
{
    const float* L  = (const float*)d_in[0];
    const float* H  = (const float*)d_in[1];
    const float* mL = (const float*)d_in[2];
    const float* mH = (const float*)d_in[3];
    float* out = (float*)d_out;

    long long msz = (long long)in_sizes[2];
    int Lh   = (int)(sqrt((double)(msz / 2)) + 0.5);
    int rows = in_sizes[0] / Lh;             // N*C
    int nt   = Lh >> 3;                      // threads per row

    dim3 block(256);
    dim3 grid((nt + block.x - 1) / block.x, rows);
    idwt1d_db4_kernel<<<grid, block>>>(L, H, mL, mH, out, Lh);
}

// round 7
// speedup vs baseline: 1.0379x; 1.0379x over previous
#include <cuda_runtime.h>
#include <math.h>

// IDWT 1D (db4), banded synthesis:
//   even j=2i  : L[i+1]*bl1 + L[i]*bl3 + L[i-1]*bl5 + L[i-2]*bl7  (+ H w/ bh)
//   odd  j=2i+1: L[i+2]*bl0 + L[i+1]*bl2 + L[i]*bl4 + L[i-1]*bl6  (+ H w/ bh)
// Taps read from matrix row r=2 (band[k] at column k+1), via uniform __ldg
// (no shared memory, no block barrier).
//
// Each thread: 1 float4 load of L, 1 of H, halo via warp shuffle,
// 8 outputs = 2 float4 streaming stores.

__global__ void __launch_bounds__(256)
idwt1d_db4_kernel(const float* __restrict__ L,
                  const float* __restrict__ H,
                  const float* __restrict__ mL,
                  const float* __restrict__ mH,
                  float* __restrict__ out,
                  int Lh)
{
    const int W    = 2 * Lh;
    const int row  = blockIdx.y;
    const int nt   = Lh >> 2;                 // threads per row
    const int t    = blockIdx.x * blockDim.x + threadIdx.x;
    if (t >= nt) return;

    const int lane = threadIdx.x & 31;
    const int c0   = 4 * t;                   // thread owns L/H[c0 .. c0+3]

    const float* __restrict__ Lr = L + (size_t)row * Lh;
    const float* __restrict__ Hr = H + (size_t)row * Lh;

    // Data loads first — in flight while taps resolve.
    const float4 l = *reinterpret_cast<const float4*>(Lr + c0);
    const float4 h = *reinterpret_cast<const float4*>(Hr + c0);

    // Taps: uniform-address broadcast loads (row r=2, columns 1..8).
    const float* __restrict__ tl = mL + (size_t)2 * W + 1;
    const float* __restrict__ th = mH + (size_t)2 * W + 1;
    const float bl0 = __ldg(tl + 0), bl1 = __ldg(tl + 1), bl2 = __ldg(tl + 2), bl3 = __ldg(tl + 3);
    const float bl4 = __ldg(tl + 4), bl5 = __ldg(tl + 5), bl6 = __ldg(tl + 6), bl7 = __ldg(tl + 7);
    const float bh0 = __ldg(th + 0), bh1 = __ldg(th + 1), bh2 = __ldg(th + 2), bh3 = __ldg(th + 3);
    const float bh4 = __ldg(th + 4), bh5 = __ldg(th + 5), bh6 = __ldg(th + 6), bh7 = __ldg(th + 7);

    // Halo from neighboring lanes (adjacent lanes = adjacent coarse quads).
    float lm2 = __shfl_up_sync(0xffffffffu, l.z, 1);
    float lm1 = __shfl_up_sync(0xffffffffu, l.w, 1);
    float hm2 = __shfl_up_sync(0xffffffffu, h.z, 1);
    float hm1 = __shfl_up_sync(0xffffffffu, h.w, 1);
    float lp4 = __shfl_down_sync(0xffffffffu, l.x, 1);
    float lp5 = __shfl_down_sync(0xffffffffu, l.y, 1);
    float hp4 = __shfl_down_sync(0xffffffffu, h.x, 1);
    float hp5 = __shfl_down_sync(0xffffffffu, h.y, 1);

    if (lane == 0) {                          // warp-edge fixups (rare lanes)
        lm2 = (c0 >= 2) ? __ldg(Lr + c0 - 2) : 0.0f;
        lm1 = (c0 >= 1) ? __ldg(Lr + c0 - 1) : 0.0f;
        hm2 = (c0 >= 2) ? __ldg(Hr + c0 - 2) : 0.0f;
        hm1 = (c0 >= 1) ? __ldg(Hr + c0 - 1) : 0.0f;
    }
    if (lane == 31) {
        lp4 = (c0 + 4 < Lh) ? __ldg(Lr + c0 + 4) : 0.0f;
        lp5 = (c0 + 5 < Lh) ? __ldg(Lr + c0 + 5) : 0.0f;
        hp4 = (c0 + 4 < Lh) ? __ldg(Hr + c0 + 4) : 0.0f;
        hp5 = (c0 + 5 < Lh) ? __ldg(Hr + c0 + 5) : 0.0f;
    }

    // la[k] = L[c0-2+k], k=0..7
    const float la[8] = { lm2, lm1, l.x, l.y, l.z, l.w, lp4, lp5 };
    const float ha[8] = { hm2, hm1, h.x, h.y, h.z, h.w, hp4, hp5 };

    float o[8];
#pragma unroll
    for (int m = 0; m < 4; m++) {
        // even j = 2*(c0+m): taps la[m..m+3]
        o[2 * m] =
            fmaf(la[m + 3], bl1, fmaf(la[m + 2], bl3, fmaf(la[m + 1], bl5, la[m] * bl7))) +
            fmaf(ha[m + 3], bh1, fmaf(ha[m + 2], bh3, fmaf(ha[m + 1], bh5, ha[m] * bh7)));
        // odd j = 2*(c0+m)+1: taps la[m+1..m+4]
        o[2 * m + 1] =
            fmaf(la[m + 4], bl0, fmaf(la[m + 3], bl2, fmaf(la[m + 2], bl4, la[m + 1] * bl6))) +
            fmaf(ha[m + 4], bh0, fmaf(ha[m + 3], bh2, fmaf(ha[m + 2], bh4, ha[m + 1] * bh6)));
    }

    float4* op = reinterpret_cast<float4*>(out + (size_t)row * W + 8 * (size_t)t);
    __stcs(op,     make_float4(o[0], o[1], o[2], o[3]));
    __stcs(op + 1, make_float4(o[4], o[5], o[6], o[7]));
}

extern "C" void kernel_launch(void* const* d_in, const int* in_sizes, int n_in,
                              void* d_out, int out_size)
{
    const float* L  = (const float*)d_in[0];
    const float* H  = (const float*)d_in[1];
    const float* mL = (const float*)d_in[2];
    const float* mH = (const float*)d_in[3];
    float* out = (float*)d_out;

    long long msz = (long long)in_sizes[2];
    int Lh   = (int)(sqrt((double)(msz / 2)) + 0.5);
    int rows = in_sizes[0] / Lh;              // N*C
    int nt   = Lh >> 2;                       // threads per row

    dim3 block(256);
    dim3 grid((nt + block.x - 1) / block.x, rows);
    idwt1d_db4_kernel<<<grid, block>>>(L, H, mL, mH, out, Lh);
}

// round 10
// speedup vs baseline: 1.3185x; 1.2704x over previous
#include <cuda_runtime.h>
#include <math.h>

// IDWT 1D (db4), banded synthesis:
//   even j=2i  : L[i+1]*bl1 + L[i]*bl3 + L[i-1]*bl5 + L[i-2]*bl7  (+ H w/ bh)
//   odd  j=2i+1: L[i+2]*bl0 + L[i+1]*bl2 + L[i]*bl4 + L[i-1]*bl6  (+ H w/ bh)
//
// Taps are the fixed db4 synthesis filters (band_low/high = DEC_LO/HI
// reversed; bl[k] = DEC_LO[7-k], bh[k] = DEC_HI[7-k]) — compile-time
// immediates, so FMAs use the fast FFMA-imm form and no tap loads exist.
//
// Each thread: 1 float4 load of L, 1 of H, halo via warp shuffle,
// 8 outputs = 2 float4 streaming stores.

#define BL0  0.23037781330885523f
#define BL1  0.7148465705525415f
#define BL2  0.6308807679295904f
#define BL3 -0.02798376941698385f
#define BL4 -0.18703481171888114f
#define BL5  0.030841381835986965f
#define BL6  0.032883011666982945f
#define BL7 -0.010597401784997278f

#define BH0 -0.010597401784997278f
#define BH1  0.032883011666982945f
#define BH2  0.030841381835986965f
#define BH3  0.18703481171888114f
#define BH4 -0.02798376941698385f
#define BH5 -0.6308807679295904f
#define BH6  0.7148465705525415f
#define BH7 -0.23037781330885523f

__global__ void __launch_bounds__(256, 7)
idwt1d_db4_kernel(const float* __restrict__ L,
                  const float* __restrict__ H,
                  float* __restrict__ out,
                  int Lh)
{
    const int W    = 2 * Lh;
    const int row  = blockIdx.y;
    const int nt   = Lh >> 2;                 // threads per row
    const int t    = blockIdx.x * blockDim.x + threadIdx.x;
    if (t >= nt) return;

    const int lane = threadIdx.x & 31;
    const int c0   = 4 * t;                   // thread owns L/H[c0 .. c0+3]

    const float* __restrict__ Lr = L + (size_t)row * Lh;
    const float* __restrict__ Hr = H + (size_t)row * Lh;

    const float4 l = *reinterpret_cast<const float4*>(Lr + c0);
    const float4 h = *reinterpret_cast<const float4*>(Hr + c0);

    // Halo from neighboring lanes (adjacent lanes = adjacent coarse quads).
    float lm2 = __shfl_up_sync(0xffffffffu, l.z, 1);
    float lm1 = __shfl_up_sync(0xffffffffu, l.w, 1);
    float hm2 = __shfl_up_sync(0xffffffffu, h.z, 1);
    float hm1 = __shfl_up_sync(0xffffffffu, h.w, 1);
    float lp4 = __shfl_down_sync(0xffffffffu, l.x, 1);
    float lp5 = __shfl_down_sync(0xffffffffu, l.y, 1);
    float hp4 = __shfl_down_sync(0xffffffffu, h.x, 1);
    float hp5 = __shfl_down_sync(0xffffffffu, h.y, 1);

    // Warp-edge fixups; hoisted predicates so these compile to predicated
    // loads instead of BSSY/BSYNC divergence regions.
    const bool e0a = (lane == 0) && (c0 >= 2);
    const bool e0b = (lane == 0) && (c0 >= 1);
    const bool e1a = (lane == 31) && (c0 + 4 < Lh);
    const bool e1b = (lane == 31) && (c0 + 5 < Lh);
    if (lane == 0)  { lm2 = 0.0f; lm1 = 0.0f; hm2 = 0.0f; hm1 = 0.0f; }
    if (lane == 31) { lp4 = 0.0f; lp5 = 0.0f; hp4 = 0.0f; hp5 = 0.0f; }
    if (e0a) { lm2 = __ldg(Lr + c0 - 2); hm2 = __ldg(Hr + c0 - 2); }
    if (e0b) { lm1 = __ldg(Lr + c0 - 1); hm1 = __ldg(Hr + c0 - 1); }
    if (e1a) { lp4 = __ldg(Lr + c0 + 4); hp4 = __ldg(Hr + c0 + 4); }
    if (e1b) { lp5 = __ldg(Lr + c0 + 5); hp5 = __ldg(Hr + c0 + 5); }

    // la[k] = L[c0-2+k], k=0..7
    const float la[8] = { lm2, lm1, l.x, l.y, l.z, l.w, lp4, lp5 };
    const float ha[8] = { hm2, hm1, h.x, h.y, h.z, h.w, hp4, hp5 };

    float o[8];
#pragma unroll
    for (int m = 0; m < 4; m++) {
        // even j = 2*(c0+m): taps la[m..m+3]
        o[2 * m] =
            fmaf(la[m + 3], BL1, fmaf(la[m + 2], BL3, fmaf(la[m + 1], BL5, la[m] * BL7))) +
            fmaf(ha[m + 3], BH1, fmaf(ha[m + 2], BH3, fmaf(ha[m + 1], BH5, ha[m] * BH7)));
        // odd j = 2*(c0+m)+1: taps la[m+1..m+4]
        o[2 * m + 1] =
            fmaf(la[m + 4], BL0, fmaf(la[m + 3], BL2, fmaf(la[m + 2], BL4, la[m + 1] * BL6))) +
            fmaf(ha[m + 4], BH0, fmaf(ha[m + 3], BH2, fmaf(ha[m + 2], BH4, ha[m + 1] * BH6)));
    }

    float4* op = reinterpret_cast<float4*>(out + (size_t)row * W + 8 * (size_t)t);
    __stcs(op,     make_float4(o[0], o[1], o[2], o[3]));
    __stcs(op + 1, make_float4(o[4], o[5], o[6], o[7]));
}

extern "C" void kernel_launch(void* const* d_in, const int* in_sizes, int n_in,
                              void* d_out, int out_size)
{
    const float* L = (const float*)d_in[0];
    const float* H = (const float*)d_in[1];
    float* out = (float*)d_out;

    long long msz = (long long)in_sizes[2];
    int Lh   = (int)(sqrt((double)(msz / 2)) + 0.5);
    int rows = in_sizes[0] / Lh;              // N*C
    int nt   = Lh >> 2;                       // threads per row

    dim3 block(256);
    dim3 grid((nt + block.x - 1) / block.x, rows);
    idwt1d_db4_kernel<<<grid, block>>>(L, H, out, Lh);
}